// round 13
// baseline (speedup 1.0000x reference)
#include <cuda_runtime.h>

#define TW 32
#define TH 64
#define HALO 5
#define RW (TW + 2*HALO)      // 42
#define RH (TH + 2*HALO)      // 74
#define NT 512
#define IMG 512
#define PLANE (IMG*IMG)

#define SSIM_C1 0.0001f
#define SSIM_C2 0.0009f

#define HBS 33                // hb row stride in float4 (padded)
// smem: float2 raw[RH*RW] = 24864 B ; float4 hb[RH*HBS] = 39072 B ; total 63936 B
#define RAW_N (RH*RW)
#define SMEM_BYTES (RAW_N*8 + RH*HBS*16)

// 11-tap gaussian, sigma=1.5, normalized; symmetric
__device__ __forceinline__ constexpr float wk(int k) {
    constexpr float W6[6] = { 0.00102838f, 0.00759876f, 0.03600077f,
                              0.10936078f, 0.21300553f, 0.26601171f };
    return W6[k < 6 ? k : 10 - k];
}

__global__ void __launch_bounds__(NT, 3)
ssim_kernel(const float* __restrict__ x, const float* __restrict__ y,
            float* __restrict__ out)
{
    extern __shared__ float smem[];
    float2* raw = (float2*)smem;                 // RH*RW  {x,y}
    float4* hb4 = (float4*)(smem + RAW_N*2);     // RH*HBS {hx,hy,hs,hxy}

    const int tid   = threadIdx.x;
    const int bx    = blockIdx.x;                // 0..15
    const int by    = blockIdx.y;                // 0..7
    const int plane = blockIdx.z;                // 0..47

    const float* __restrict__ xp = x + (size_t)plane * PLANE;
    const float* __restrict__ yp = y + (size_t)plane * PLANE;

    const int gx0 = bx * TW - HALO;
    const int gy0 = by * TH - HALO;

    const bool interior = (gx0 >= 0) & (gy0 >= 0) &
                          (gx0 + RW <= IMG) & (gy0 + RH <= IMG);

    // ---------------- Stage 1: gmem -> smem raw tile ----------------------
    if (interior) {
        // 518 one-shot tasks: 74 rows x 7 groups of 6 cols.
        // 12 independent LDG.32 batched (MLP=12), then 3 STS.128.
        #pragma unroll
        for (int rep = 0; rep < 2; ++rep) {
            const int t = tid + rep * NT;
            if (rep == 1 && tid >= 518 - NT) break;   // only 6 threads repeat
            if (t < 518) {
                const int r  = t / 7;                 // mul-shift (const 7)
                const int c0 = (t - 7 * r) * 6;       // 0,6,...,36
                const float* xr = xp + (gy0 + r) * IMG + gx0 + c0;
                const float* yr = yp + (gy0 + r) * IMG + gx0 + c0;
                float x0 = __ldg(xr + 0), x1 = __ldg(xr + 1), x2 = __ldg(xr + 2);
                float x3 = __ldg(xr + 3), x4 = __ldg(xr + 4), x5 = __ldg(xr + 5);
                float y0 = __ldg(yr + 0), y1 = __ldg(yr + 1), y2 = __ldg(yr + 2);
                float y3 = __ldg(yr + 3), y4 = __ldg(yr + 4), y5 = __ldg(yr + 5);
                float4* wp = (float4*)&raw[r * RW + c0];   // 16B aligned (c0 even)
                wp[0] = make_float4(x0, y0, x1, y1);
                wp[1] = make_float4(x2, y2, x3, y3);
                wp[2] = make_float4(x4, y4, x5, y5);
            }
        }
    } else {
        #pragma unroll 1
        for (int i = tid; i < RAW_N; i += NT) {
            int r = i / RW;
            int c = i - r * RW;
            int gr = gy0 + r, gc = gx0 + c;
            float xv = 0.f, yv = 0.f;
            if ((unsigned)gr < (unsigned)IMG && (unsigned)gc < (unsigned)IMG) {
                int off = gr * IMG + gc;
                xv = __ldg(xp + off);
                yv = __ldg(yp + off);
            }
            raw[i] = make_float2(xv, yv);
        }
    }
    __syncthreads();

    // ---------------- Stage 2: horizontal 11-tap, 4-col register block ----
    // tasks: 8 col-groups x 74 rows = 592; lanes map to consecutive ROWS
    // within a group -> conflict-free STS.128 / LDS.128 phases.
    #pragma unroll 1
    for (int t = tid; t < 8*RH; t += NT) {
        const int gq  = t / RH;              // column group 0..7
        const int row = t - gq * RH;         // 0..73
        const float4* rp4 = (const float4*)(raw + row * RW + 4*gq);

        float a0[4] = {0,0,0,0};   // hblur(x)
        float a1[4] = {0,0,0,0};   // hblur(y)
        float a2[4] = {0,0,0,0};   // hblur(x^2 + y^2)
        float a3[4] = {0,0,0,0};   // hblur(x*y)

        #pragma unroll
        for (int q = 0; q < 7; ++q) {        // 7 x LDS.128 = 14 taps
            float4 pr = rp4[q];              // {x0,y0,x1,y1} = taps 2q, 2q+1
            #pragma unroll
            for (int h = 0; h < 2; ++h) {
                const int p = 2*q + h;
                float vx = h ? pr.z : pr.x;
                float vy = h ? pr.w : pr.y;
                float s  = fmaf(vy, vy, vx * vx);
                float xy = vx * vy;
                #pragma unroll
                for (int i2 = 0; i2 < 4; ++i2) {
                    int k = p - i2;
                    if (k >= 0 && k <= 10) {
                        a0[i2] = fmaf(vx, wk(k), a0[i2]);
                        a1[i2] = fmaf(vy, wk(k), a1[i2]);
                        a2[i2] = fmaf(s,  wk(k), a2[i2]);
                        a3[i2] = fmaf(xy, wk(k), a3[i2]);
                    }
                }
            }
        }

        float4* hp = hb4 + row * HBS + 4*gq;
        #pragma unroll
        for (int i2 = 0; i2 < 4; ++i2)
            hp[i2] = make_float4(a0[i2], a1[i2], a2[i2], a3[i2]);
    }
    __syncthreads();

    // ---------------- Stage 3: vertical 11-tap, 4-row block, LDS.128 taps -
    {
        const int col = tid & 31;
        const int r0  = (tid >> 5) * 4;     // 16 segments * 4 rows = 64

        float b0[4] = {0,0,0,0}, b1[4] = {0,0,0,0},
              b2[4] = {0,0,0,0}, b3[4] = {0,0,0,0};

        const float4* hp = hb4 + r0 * HBS + col;
        #pragma unroll
        for (int p = 0; p < 14; ++p) {
            float4 h = hp[p * HBS];          // one LDS.128: all 4 quantities
            #pragma unroll
            for (int i2 = 0; i2 < 4; ++i2) {
                int k = p - i2;
                if (k >= 0 && k <= 10) {
                    b0[i2] = fmaf(h.x, wk(k), b0[i2]);
                    b1[i2] = fmaf(h.y, wk(k), b1[i2]);
                    b2[i2] = fmaf(h.z, wk(k), b2[i2]);
                    b3[i2] = fmaf(h.w, wk(k), b3[i2]);
                }
            }
        }

        float* op = out + (size_t)plane * PLANE
                        + (size_t)(by * TH + r0) * IMG
                        + bx * TW + col;

        #pragma unroll
        for (int i2 = 0; i2 < 4; ++i2) {
            float mu1  = b0[i2];
            float mu2  = b1[i2];
            float m12  = mu1 * mu2;
            float m11  = mu1 * mu1;
            float m22  = mu2 * mu2;
            float ssum = b2[i2] - m11 - m22;    // sigma1^2 + sigma2^2
            float s12  = b3[i2] - m12;
            float num = fmaf(2.f, m12, SSIM_C1) * fmaf(2.f, s12, SSIM_C2);
            float den = (m11 + m22 + SSIM_C1) * (ssum + SSIM_C2);
            op[(size_t)i2 * IMG] = __fdividef(num, den);
        }
    }
}

extern "C" void kernel_launch(void* const* d_in, const int* in_sizes, int n_in,
                              void* d_out, int out_size)
{
    const float* x = (const float*)d_in[0];   // img_out  [16,3,512,512] f32
    const float* y = (const float*)d_in[1];   // img_target
    float* out = (float*)d_out;

    int planes = in_sizes[0] / PLANE;         // 48

    cudaFuncSetAttribute(ssim_kernel,
                         cudaFuncAttributeMaxDynamicSharedMemorySize,
                         SMEM_BYTES);

    dim3 grid(IMG / TW, IMG / TH, planes);    // (16, 8, 48)
    ssim_kernel<<<grid, NT, SMEM_BYTES>>>(x, y, out);
}

// round 14
// speedup vs baseline: 1.0272x; 1.0272x over previous
#include <cuda_runtime.h>

#define TW 32
#define TH 32
#define HALO 5
#define RW (TW + 2*HALO)      // 42
#define RH (TH + 2*HALO)      // 42
#define NT 512
#define IMG 512
#define PLANE (IMG*IMG)

#define SSIM_C1 0.0001f
#define SSIM_C2 0.0009f

#define HBS 33                // hb row stride in float4 (padded)
// smem: float2 raw[RH*RW] = 14112 B ; float4 hb[RH*HBS] = 22176 B ; total 36288 B
// -> 4 CTAs/SM x 512 threads = 2048 threads (100% occupancy)
#define RAW_N (RH*RW)
#define SMEM_BYTES (RAW_N*8 + RH*HBS*16)

// 11-tap gaussian, sigma=1.5, normalized; symmetric
__device__ __forceinline__ constexpr float wk(int k) {
    constexpr float W6[6] = { 0.00102838f, 0.00759876f, 0.03600077f,
                              0.10936078f, 0.21300553f, 0.26601171f };
    return W6[k < 6 ? k : 10 - k];
}

__global__ void __launch_bounds__(NT, 4)
ssim_kernel(const float* __restrict__ x, const float* __restrict__ y,
            float* __restrict__ out)
{
    extern __shared__ float smem[];
    float2* raw = (float2*)smem;                 // RH*RW  {x,y}
    float4* hb4 = (float4*)(smem + RAW_N*2);     // RH*HBS {hx,hy,hs,hxy}

    const int tid   = threadIdx.x;
    const int bx    = blockIdx.x;                // 0..15
    const int by    = blockIdx.y;                // 0..15
    const int plane = blockIdx.z;                // 0..47

    const float* __restrict__ xp = x + (size_t)plane * PLANE;
    const float* __restrict__ yp = y + (size_t)plane * PLANE;

    const int gx0 = bx * TW - HALO;
    const int gy0 = by * TH - HALO;

    const bool interior = (gx0 >= 0) & (gy0 >= 0) &
                          (gx0 + RW <= IMG) & (gy0 + RH <= IMG);

    // ---------------- Stage 1: gmem -> smem raw tile ----------------------
    if (interior) {
        // pair-granular: 21 column-pairs x 42 rows = 882 tasks, divless walk
        int r = tid / 21;
        int c = tid - r * 21;                // pair index 0..20
        #pragma unroll 1
        while (r < RH) {
            const float* xq = xp + (gy0 + r) * IMG + gx0 + 2*c;
            const float* yq = yp + (gy0 + r) * IMG + gx0 + 2*c;
            float x0 = __ldg(xq);
            float x1 = __ldg(xq + 1);
            float y0 = __ldg(yq);
            float y1 = __ldg(yq + 1);
            *(float4*)&raw[r * RW + 2*c] = make_float4(x0, y0, x1, y1);
            r += 24; c += 8;                 // advance 512 = 24*21 + 8
            if (c >= 21) { c -= 21; r += 1; }
        }
    } else {
        #pragma unroll 1
        for (int i = tid; i < RAW_N; i += NT) {
            int r = i / RW;
            int c = i - r * RW;
            int gr = gy0 + r, gc = gx0 + c;
            float xv = 0.f, yv = 0.f;
            if ((unsigned)gr < (unsigned)IMG && (unsigned)gc < (unsigned)IMG) {
                int off = gr * IMG + gc;
                xv = __ldg(xp + off);
                yv = __ldg(yp + off);
            }
            raw[i] = make_float2(xv, yv);
        }
    }
    __syncthreads();

    // ---------------- Stage 2: horizontal 11-tap, 4-col register block ----
    // 8 col-groups x 42 rows = 336 tasks, single pass; lanes map to
    // consecutive ROWS within a group -> conflict-free LDS/STS phases.
    if (tid < 8*RH) {
        const int gq  = tid / RH;            // column group 0..7
        const int row = tid - gq * RH;       // 0..41
        const float4* rp4 = (const float4*)(raw + row * RW + 4*gq);

        float a0[4] = {0,0,0,0};   // hblur(x)
        float a1[4] = {0,0,0,0};   // hblur(y)
        float a2[4] = {0,0,0,0};   // hblur(x^2 + y^2)
        float a3[4] = {0,0,0,0};   // hblur(x*y)

        #pragma unroll
        for (int q = 0; q < 7; ++q) {        // 7 x LDS.128 = 14 taps
            float4 pr = rp4[q];              // {x0,y0,x1,y1} = taps 2q, 2q+1
            #pragma unroll
            for (int h = 0; h < 2; ++h) {
                const int p = 2*q + h;
                float vx = h ? pr.z : pr.x;
                float vy = h ? pr.w : pr.y;
                float s  = fmaf(vy, vy, vx * vx);
                float xy = vx * vy;
                #pragma unroll
                for (int i2 = 0; i2 < 4; ++i2) {
                    int k = p - i2;
                    if (k >= 0 && k <= 10) {
                        a0[i2] = fmaf(vx, wk(k), a0[i2]);
                        a1[i2] = fmaf(vy, wk(k), a1[i2]);
                        a2[i2] = fmaf(s,  wk(k), a2[i2]);
                        a3[i2] = fmaf(xy, wk(k), a3[i2]);
                    }
                }
            }
        }

        float4* hp = hb4 + row * HBS + 4*gq;
        #pragma unroll
        for (int i2 = 0; i2 < 4; ++i2)
            hp[i2] = make_float4(a0[i2], a1[i2], a2[i2], a3[i2]);
    }
    __syncthreads();

    // ---------------- Stage 3: vertical 11-tap, 4-row block, LDS.128 taps -
    // 32 cols x 8 segments = 256 tasks on threads 0..255.
    if (tid < 256) {
        const int col = tid & 31;
        const int r0  = (tid >> 5) * 4;     // 8 segments * 4 rows = 32

        float b0[4] = {0,0,0,0}, b1[4] = {0,0,0,0},
              b2[4] = {0,0,0,0}, b3[4] = {0,0,0,0};

        const float4* hp = hb4 + r0 * HBS + col;
        #pragma unroll
        for (int p = 0; p < 14; ++p) {
            float4 h = hp[p * HBS];          // one LDS.128: all 4 quantities
            #pragma unroll
            for (int i2 = 0; i2 < 4; ++i2) {
                int k = p - i2;
                if (k >= 0 && k <= 10) {
                    b0[i2] = fmaf(h.x, wk(k), b0[i2]);
                    b1[i2] = fmaf(h.y, wk(k), b1[i2]);
                    b2[i2] = fmaf(h.z, wk(k), b2[i2]);
                    b3[i2] = fmaf(h.w, wk(k), b3[i2]);
                }
            }
        }

        float* op = out + (size_t)plane * PLANE
                        + (size_t)(by * TH + r0) * IMG
                        + bx * TW + col;

        #pragma unroll
        for (int i2 = 0; i2 < 4; ++i2) {
            float mu1  = b0[i2];
            float mu2  = b1[i2];
            float m12  = mu1 * mu2;
            float m11  = mu1 * mu1;
            float m22  = mu2 * mu2;
            float ssum = b2[i2] - m11 - m22;    // sigma1^2 + sigma2^2
            float s12  = b3[i2] - m12;
            float num = fmaf(2.f, m12, SSIM_C1) * fmaf(2.f, s12, SSIM_C2);
            float den = (m11 + m22 + SSIM_C1) * (ssum + SSIM_C2);
            op[(size_t)i2 * IMG] = __fdividef(num, den);
        }
    }
}

extern "C" void kernel_launch(void* const* d_in, const int* in_sizes, int n_in,
                              void* d_out, int out_size)
{
    const float* x = (const float*)d_in[0];   // img_out  [16,3,512,512] f32
    const float* y = (const float*)d_in[1];   // img_target
    float* out = (float*)d_out;

    int planes = in_sizes[0] / PLANE;         // 48

    cudaFuncSetAttribute(ssim_kernel,
                         cudaFuncAttributeMaxDynamicSharedMemorySize,
                         SMEM_BYTES);

    dim3 grid(IMG / TW, IMG / TH, planes);    // (16, 16, 48)
    ssim_kernel<<<grid, NT, SMEM_BYTES>>>(x, y, out);
}

// round 15
// speedup vs baseline: 1.0990x; 1.0699x over previous
#include <cuda_runtime.h>

#define TW 32
#define TH 32
#define HALO 5
#define RW (TW + 2*HALO)      // 42
#define RH (TH + 2*HALO)      // 42
#define NT 512
#define IMG 512
#define PLANE (IMG*IMG)

#define SSIM_C1 0.0001f
#define SSIM_C2 0.0009f

#define HBS 33                // hb row stride in float4 (padded)
// smem: float2 raw[RH*RW] = 14112 B ; float4 hb[RH*HBS] = 22176 B ; 36288 B
// -> 4 CTAs/SM x 512 threads = 2048 threads (100% occupancy)
#define RAW_N (RH*RW)
#define RAW4_N (RAW_N/2)      // 882 float4 slots
#define SMEM_BYTES (RAW_N*8 + RH*HBS*16)

// 11-tap gaussian, sigma=1.5, normalized; symmetric
__device__ __forceinline__ constexpr float wk(int k) {
    constexpr float W6[6] = { 0.00102838f, 0.00759876f, 0.03600077f,
                              0.10936078f, 0.21300553f, 0.26601171f };
    return W6[k < 6 ? k : 10 - k];
}

__global__ void __launch_bounds__(NT, 4)
ssim_kernel(const float* __restrict__ x, const float* __restrict__ y,
            float* __restrict__ out)
{
    extern __shared__ float smem[];
    float4* raw4 = (float4*)smem;                // RAW4_N {x0,y0,x1,y1}
    float4* hb4  = (float4*)(smem + RAW_N*2);    // RH*HBS {hx,hy,hs,hxy}

    const int tid   = threadIdx.x;
    const int bx    = blockIdx.x;                // 0..15
    const int by    = blockIdx.y;                // 0..15
    const int plane = blockIdx.z;                // 0..47

    const float* __restrict__ xp = x + (size_t)plane * PLANE;
    const float* __restrict__ yp = y + (size_t)plane * PLANE;

    const int gx0 = bx * TW - HALO;
    const int gy0 = by * TH - HALO;

    const bool interior = (gx0 >= 0) & (gy0 >= 0) &
                          (gx0 + RW <= IMG) & (gy0 + RH <= IMG);

    // ---------------- Stage 1: gmem -> smem raw tile ----------------------
    if (interior) {
        const int base = gy0 * IMG + gx0;        // block-uniform
        // 882 flat float4 tasks; slot i <-> (r = i/21, pair c = i%21)
        #pragma unroll
        for (int rep = 0; rep < 2; ++rep) {
            const int i = tid + rep * NT;
            if (rep == 0 || i < RAW4_N) {
                const int r  = i / 21;           // const-div -> mulhi
                const int cc = (i - r * 21) * 2;
                const int off = base + r * IMG + cc;
                float x0 = __ldg(xp + off);
                float x1 = __ldg(xp + off + 1);
                float y0 = __ldg(yp + off);
                float y1 = __ldg(yp + off + 1);
                raw4[i] = make_float4(x0, y0, x1, y1);
            }
        }
    } else {
        #pragma unroll 1
        for (int i = tid; i < RAW4_N; i += NT) {
            const int r  = i / 21;
            const int cc = (i - r * 21) * 2;
            const int gr = gy0 + r;
            const int gc0 = gx0 + cc;
            float x0 = 0.f, x1 = 0.f, y0 = 0.f, y1 = 0.f;
            if ((unsigned)gr < (unsigned)IMG) {
                const int rb = gr * IMG;
                if ((unsigned)gc0 < (unsigned)IMG) {
                    x0 = __ldg(xp + rb + gc0);
                    y0 = __ldg(yp + rb + gc0);
                }
                if ((unsigned)(gc0+1) < (unsigned)IMG) {
                    x1 = __ldg(xp + rb + gc0 + 1);
                    y1 = __ldg(yp + rb + gc0 + 1);
                }
            }
            raw4[i] = make_float4(x0, y0, x1, y1);
        }
    }
    __syncthreads();

    // ---------------- Stage 2: horizontal 11-tap, 4-col register block ----
    // 8 col-groups x 42 rows = 336 tasks, single pass; lanes map to
    // consecutive ROWS within a group -> conflict-free LDS/STS phases.
    if (tid < 8*RH) {
        const int gq  = tid / RH;            // column group 0..7
        const int row = tid - gq * RH;       // 0..41
        // raw float4 slot index: (row*RW + 4*gq)/2 = row*21 + 2*gq
        const float4* rp4 = raw4 + row * 21 + 2 * gq;

        // acc[i2] = {hx, hy, hs, hxy} accumulated in-place (STS.128 source)
        float4 acc[4];
        #pragma unroll
        for (int i2 = 0; i2 < 4; ++i2) acc[i2] = make_float4(0.f,0.f,0.f,0.f);

        #pragma unroll
        for (int q = 0; q < 7; ++q) {        // 7 x LDS.128 = 14 taps
            float4 pr = rp4[q];              // {x0,y0,x1,y1} = taps 2q, 2q+1
            #pragma unroll
            for (int h = 0; h < 2; ++h) {
                const int p = 2*q + h;
                float vx = h ? pr.z : pr.x;
                float vy = h ? pr.w : pr.y;
                float s  = fmaf(vy, vy, vx * vx);
                float xy = vx * vy;
                #pragma unroll
                for (int i2 = 0; i2 < 4; ++i2) {
                    int k = p - i2;
                    if (k >= 0 && k <= 10) {
                        acc[i2].x = fmaf(vx, wk(k), acc[i2].x);
                        acc[i2].y = fmaf(vy, wk(k), acc[i2].y);
                        acc[i2].z = fmaf(s,  wk(k), acc[i2].z);
                        acc[i2].w = fmaf(xy, wk(k), acc[i2].w);
                    }
                }
            }
        }

        float4* hp = hb4 + row * HBS + 4*gq;
        #pragma unroll
        for (int i2 = 0; i2 < 4; ++i2)
            hp[i2] = acc[i2];
    }
    __syncthreads();

    // ---------------- Stage 3: vertical 11-tap, 4-row block, LDS.128 taps -
    // 32 cols x 8 segments = 256 tasks on threads 0..255.
    if (tid < 256) {
        const int col = tid & 31;
        const int r0  = (tid >> 5) * 4;     // 8 segments * 4 rows = 32

        float b0[4] = {0,0,0,0}, b1[4] = {0,0,0,0},
              b2[4] = {0,0,0,0}, b3[4] = {0,0,0,0};

        const float4* hp = hb4 + r0 * HBS + col;
        #pragma unroll
        for (int p = 0; p < 14; ++p) {
            float4 h = hp[p * HBS];          // one LDS.128: all 4 quantities
            #pragma unroll
            for (int i2 = 0; i2 < 4; ++i2) {
                int k = p - i2;
                if (k >= 0 && k <= 10) {
                    b0[i2] = fmaf(h.x, wk(k), b0[i2]);
                    b1[i2] = fmaf(h.y, wk(k), b1[i2]);
                    b2[i2] = fmaf(h.z, wk(k), b2[i2]);
                    b3[i2] = fmaf(h.w, wk(k), b3[i2]);
                }
            }
        }

        float* op = out + (size_t)plane * PLANE
                        + (size_t)(by * TH + r0) * IMG
                        + bx * TW + col;

        #pragma unroll
        for (int i2 = 0; i2 < 4; ++i2) {
            float mu1  = b0[i2];
            float mu2  = b1[i2];
            float m12  = mu1 * mu2;
            float m11  = mu1 * mu1;
            float m22  = mu2 * mu2;
            float ssum = b2[i2] - m11 - m22;    // sigma1^2 + sigma2^2
            float s12  = b3[i2] - m12;
            float num = fmaf(2.f, m12, SSIM_C1) * fmaf(2.f, s12, SSIM_C2);
            float den = (m11 + m22 + SSIM_C1) * (ssum + SSIM_C2);
            op[(size_t)i2 * IMG] = __fdividef(num, den);
        }
    }
}

extern "C" void kernel_launch(void* const* d_in, const int* in_sizes, int n_in,
                              void* d_out, int out_size)
{
    const float* x = (const float*)d_in[0];   // img_out  [16,3,512,512] f32
    const float* y = (const float*)d_in[1];   // img_target
    float* out = (float*)d_out;

    int planes = in_sizes[0] / PLANE;         // 48

    cudaFuncSetAttribute(ssim_kernel,
                         cudaFuncAttributeMaxDynamicSharedMemorySize,
                         SMEM_BYTES);

    dim3 grid(IMG / TW, IMG / TH, planes);    // (16, 16, 48)
    ssim_kernel<<<grid, NT, SMEM_BYTES>>>(x, y, out);
}